// round 7
// baseline (speedup 1.0000x reference)
#include <cuda_runtime.h>
#include <math.h>
#include <stdint.h>

#define D_ 256
#define H_ 256
#define B_ 128
#define E_ 128
#define STEPS_ 5
#define NMAX 100352

// ---------------- scratch ----------------
__device__ __align__(16) float g_tmp[NMAX * H_];
__device__ __align__(16) float g_hfeat[NMAX * H_];
__device__ float g_hbuf[2][3][B_ * H_];
__device__ float g_c[3][B_ * H_];
__device__ float g_qstar[B_ * 2 * H_];
__device__ int   g_seg[B_ + 1];
__device__ __align__(16) float g_Wt1[D_ * H_];
__device__ __align__(16) float g_Wt2[H_ * H_];

__device__ __forceinline__ uint32_t cvt_tf32(float f) {
    uint32_t r;
    asm("cvt.rn.tf32.f32 %0, %1;" : "=r"(r) : "f"(f));
    return r;
}

// ---------------- init ----------------
__global__ void k_init() {
    int i = blockIdx.x * blockDim.x + threadIdx.x;
    int stride = gridDim.x * blockDim.x;
    for (int j = i; j < B_ * 2 * H_; j += stride) g_qstar[j] = 0.f;
    for (int j = i; j < 3 * B_ * H_; j += stride) {
        g_hbuf[0][0][j] = 0.f;
        g_hbuf[1][0][j] = 0.f;
        g_c[0][j] = 0.f;
    }
}

// ---------------- weight transpose + tf32 round ----------------
__global__ void k_transpose(const float* __restrict__ W1, const float* __restrict__ W2,
                            float* __restrict__ Wt1, float* __restrict__ Wt2) {
    __shared__ float t[32][33];
    const float* W  = blockIdx.z ? W2  : W1;
    float*       Wt = blockIdx.z ? Wt2 : Wt1;
    int bx = blockIdx.x * 32, by = blockIdx.y * 32;
    int tx = threadIdx.x, ty = threadIdx.y;
    t[ty][tx] = W[(by + ty) * 256 + bx + tx];
    __syncthreads();
    Wt[(bx + ty) * 256 + by + tx] = __uint_as_float(cvt_tf32(t[tx][ty]));
}

// ---------------- segment offsets ----------------
__global__ void k_seg(const int* __restrict__ idx, int N) {
    int b = threadIdx.x;
    if (b > B_) return;
    int lo = 0, hi = N;
    while (lo < hi) {
        int mid = (lo + hi) >> 1;
        if (idx[mid] < b) lo = mid + 1; else hi = mid;
    }
    g_seg[b] = lo;
}

// ---------------- FNN GEMM: tf32 HMMA, 3-stage cp.async, 2 CTA/SM ------------
#define KC 32
#define LDT 36
#define SM_STAGE (128 * LDT)              // floats per (A or B) tile
#define SM_BYTES (3 * 2 * SM_STAGE * 4)   // 110592 B

template <bool ELU, bool ROUND_OUT>
__global__ __launch_bounds__(256) void k_fnn_mma(
    const float* __restrict__ A, const float* __restrict__ Wt,
    const float* __restrict__ bias, float* __restrict__ C, int nrows)
{
    extern __shared__ float smem[];
    __shared__ float bias_s[128];

    const int tid  = threadIdx.x;
    const int lane = tid & 31;
    const int warp = tid >> 5;
    const int wm = warp >> 2;
    const int wn = warp & 3;
    const int row0 = blockIdx.x * 128;
    const int col0 = blockIdx.y * 128;

    if (tid < 128) bias_s[tid] = bias[col0 + tid];

    float acc[4][4][4];
#pragma unroll
    for (int mi = 0; mi < 4; mi++)
#pragma unroll
        for (int ni = 0; ni < 4; ni++)
#pragma unroll
            for (int j = 0; j < 4; j++) acc[mi][ni][j] = 0.f;

    const int qr = lane >> 2;
    const int qc = lane & 3;
    const int ldr = tid >> 3;          // 0..31
    const int ldq = (tid & 7) * 4;     // 0,4,..,28

    auto stage = [&](int kc, int s) {
        float* bufA = smem + s * 2 * SM_STAGE;
        float* bufB = bufA + SM_STAGE;
#pragma unroll
        for (int i = 0; i < 4; i++) {
            int r = ldr + 32 * i;
            int gr = row0 + r; if (gr >= nrows) gr = nrows - 1;
            uint32_t d = (uint32_t)__cvta_generic_to_shared(bufA + r * LDT + ldq);
            const float* sp = A + (size_t)gr * 256 + kc + ldq;
            asm volatile("cp.async.cg.shared.global [%0], [%1], 16;" :: "r"(d), "l"(sp) : "memory");
        }
#pragma unroll
        for (int i = 0; i < 4; i++) {
            int r = ldr + 32 * i;
            uint32_t d = (uint32_t)__cvta_generic_to_shared(bufB + r * LDT + ldq);
            const float* sp = Wt + (size_t)(col0 + r) * 256 + kc + ldq;
            asm volatile("cp.async.cg.shared.global [%0], [%1], 16;" :: "r"(d), "l"(sp) : "memory");
        }
        asm volatile("cp.async.commit_group;" ::: "memory");
    };

    stage(0, 0);
    stage(KC, 1);
    for (int c = 0; c < 8; c++) {
        if (c < 6) {
            stage((c + 2) * KC, (c + 2) % 3);
            asm volatile("cp.async.wait_group 2;" ::: "memory");
        } else if (c == 6) {
            asm volatile("cp.async.wait_group 1;" ::: "memory");
        } else {
            asm volatile("cp.async.wait_group 0;" ::: "memory");
        }
        __syncthreads();
        const float* As = smem + (c % 3) * 2 * SM_STAGE;
        const float* Bs = As + SM_STAGE;
#pragma unroll
        for (int ks = 0; ks < KC; ks += 8) {
            uint32_t af[4][4], bf[4][2];
#pragma unroll
            for (int mi = 0; mi < 4; mi++) {
                const float* ab = As + (wm * 64 + mi * 16) * LDT + ks;
                af[mi][0] = __float_as_uint(ab[qr * LDT + qc]);
                af[mi][1] = __float_as_uint(ab[(qr + 8) * LDT + qc]);
                af[mi][2] = __float_as_uint(ab[qr * LDT + qc + 4]);
                af[mi][3] = __float_as_uint(ab[(qr + 8) * LDT + qc + 4]);
            }
#pragma unroll
            for (int ni = 0; ni < 4; ni++) {
                const float* bb = Bs + (wn * 32 + ni * 8 + qr) * LDT + ks;
                bf[ni][0] = __float_as_uint(bb[qc]);
                bf[ni][1] = __float_as_uint(bb[qc + 4]);
            }
#pragma unroll
            for (int mi = 0; mi < 4; mi++)
#pragma unroll
                for (int ni = 0; ni < 4; ni++) {
                    asm volatile(
                        "mma.sync.aligned.m16n8k8.row.col.f32.tf32.tf32.f32 "
                        "{%0,%1,%2,%3}, {%4,%5,%6,%7}, {%8,%9}, {%0,%1,%2,%3};"
                        : "+f"(acc[mi][ni][0]), "+f"(acc[mi][ni][1]),
                          "+f"(acc[mi][ni][2]), "+f"(acc[mi][ni][3])
                        : "r"(af[mi][0]), "r"(af[mi][1]), "r"(af[mi][2]), "r"(af[mi][3]),
                          "r"(bf[ni][0]), "r"(bf[ni][1]));
                }
        }
        __syncthreads();
    }

#pragma unroll
    for (int mi = 0; mi < 4; mi++) {
        int r0 = row0 + wm * 64 + mi * 16 + qr;
#pragma unroll
        for (int ni = 0; ni < 4; ni++) {
            int cl = wn * 32 + ni * 8 + qc * 2;
            float b0 = bias_s[cl], b1 = bias_s[cl + 1];
            float v0 = acc[mi][ni][0] + b0, v1 = acc[mi][ni][1] + b1;
            float v2 = acc[mi][ni][2] + b0, v3 = acc[mi][ni][3] + b1;
            if (ELU) {
                v0 = (v0 > 0.f) ? v0 : expm1f(v0);
                v1 = (v1 > 0.f) ? v1 : expm1f(v1);
                v2 = (v2 > 0.f) ? v2 : expm1f(v2);
                v3 = (v3 > 0.f) ? v3 : expm1f(v3);
            }
            if (ROUND_OUT) {
                v0 = __uint_as_float(cvt_tf32(v0));
                v1 = __uint_as_float(cvt_tf32(v1));
                v2 = __uint_as_float(cvt_tf32(v2));
                v3 = __uint_as_float(cvt_tf32(v3));
            }
            int cg = col0 + cl;
            if (r0 < nrows)
                *(float2*)(C + (size_t)r0 * 256 + cg) = make_float2(v0, v1);
            if (r0 + 8 < nrows)
                *(float2*)(C + (size_t)(r0 + 8) * 256 + cg) = make_float2(v2, v3);
        }
    }
}

// ---------------- fused LSTM layer: gates GEMM + cell update -----------------
// grid (B/32, H/16), 256 threads (tx=hidden 0..15, ty=row 0..15, 2 rows/thread).
// Gate-grouped tiling: thread owns i,f,g,o of hidden unit j -> inline update.
__global__ __launch_bounds__(256) void k_lstm(
    const float* __restrict__ xin, int KW,
    const float* __restrict__ hold,
    const float* __restrict__ Wih, const float* __restrict__ Whh,
    const float* __restrict__ bih, const float* __restrict__ bhh,
    float* __restrict__ c, float* __restrict__ hnew,
    float* __restrict__ qdst)
{
    __shared__ float a_s[32][33];
    __shared__ float w_s[4][16][33];
    const int tid = threadIdx.x;
    const int tx = tid & 15;          // hidden unit within tile
    const int ty = tid >> 4;          // 0..15 -> rows ty, ty+16
    const int b0 = blockIdx.x * 32;
    const int j0 = blockIdx.y * 16;
    const int KT = KW + H_;

    float ac[2][4];
#pragma unroll
    for (int r = 0; r < 2; r++)
#pragma unroll
        for (int g = 0; g < 4; g++) ac[r][g] = 0.f;

    const int alr = tid >> 3, alc = (tid & 7) * 4;   // A: 32 rows x 8 f4
    for (int kt = 0; kt < KT; kt += 32) {
        const float *Asrc, *Wsrc; int k, str;
        if (kt < KW) { Asrc = xin;  Wsrc = Wih; k = kt;      str = KW; }
        else         { Asrc = hold; Wsrc = Whh; k = kt - KW; str = H_; }
        // A tile 32x32: 1 float4 per thread
        {
            float4 v = *(const float4*)(Asrc + (size_t)(b0 + alr) * str + k + alc);
            a_s[alr][alc + 0] = v.x; a_s[alr][alc + 1] = v.y;
            a_s[alr][alc + 2] = v.z; a_s[alr][alc + 3] = v.w;
        }
        // W tiles 4x16x32: 2 float4 per thread (512 f4 total)
#pragma unroll
        for (int i = 0; i < 2; i++) {
            int idx = tid + 256 * i;          // 0..511
            int row = idx >> 3;               // 0..63
            int q = (idx & 7) * 4;
            int g = row >> 4, lr = row & 15;
            float4 v = *(const float4*)(Wsrc + (size_t)(g * 256 + j0 + lr) * str + k + q);
            w_s[g][lr][q + 0] = v.x; w_s[g][lr][q + 1] = v.y;
            w_s[g][lr][q + 2] = v.z; w_s[g][lr][q + 3] = v.w;
        }
        __syncthreads();
#pragma unroll
        for (int kk = 0; kk < 32; kk++) {
            float a0 = a_s[ty][kk], a1 = a_s[ty + 16][kk];
            float w0 = w_s[0][tx][kk], w1 = w_s[1][tx][kk];
            float w2 = w_s[2][tx][kk], w3 = w_s[3][tx][kk];
            ac[0][0] += a0 * w0; ac[0][1] += a0 * w1;
            ac[0][2] += a0 * w2; ac[0][3] += a0 * w3;
            ac[1][0] += a1 * w0; ac[1][1] += a1 * w1;
            ac[1][2] += a1 * w2; ac[1][3] += a1 * w3;
        }
        __syncthreads();
    }

    // cell update
    const int j = j0 + tx;
    float bi = bih[j]       + bhh[j];
    float bff = bih[256 + j] + bhh[256 + j];
    float bg = bih[512 + j] + bhh[512 + j];
    float bo = bih[768 + j] + bhh[768 + j];
#pragma unroll
    for (int r = 0; r < 2; r++) {
        int rb = b0 + ty + 16 * r;
        float iv = ac[r][0] + bi;
        float fv = ac[r][1] + bff;
        float gv = ac[r][2] + bg;
        float ov = ac[r][3] + bo;
        float sigi = 1.f / (1.f + expf(-iv));
        float sigf_ = 1.f / (1.f + expf(-fv));
        float sigo = 1.f / (1.f + expf(-ov));
        float cn = sigf_ * c[rb * H_ + j] + sigi * tanhf(gv);
        c[rb * H_ + j] = cn;
        float hn = sigo * tanhf(cn);
        hnew[rb * H_ + j] = hn;
        if (qdst) qdst[rb * 2 * H_ + j] = hn;
    }
}

// ---------------- segment attention: online softmax, 128-node chunks ---------
__global__ __launch_bounds__(512) void k_attn(
    const float* __restrict__ hfeat, const float* __restrict__ q,
    float* __restrict__ qstar)
{
    const int b = blockIdx.x, tid = threadIdx.x;
    const int s0 = g_seg[b], s1 = g_seg[b + 1];
    __shared__ float q_s[256];
    __shared__ float e_s[2][128];
    __shared__ float ws[2][128];
    __shared__ float racc[256];
    __shared__ float red[18];
    if (tid < 256) q_s[tid] = q[b * 256 + tid];
    __syncthreads();

    const int lane = tid & 31, warp = tid >> 5;
    const int col = tid & 255, half = tid >> 8;
    float qreg[8];
#pragma unroll
    for (int k = 0; k < 8; k++) qreg[k] = q_s[lane + 32 * k];

    float acc = 0.f, dpart = 0.f, m = -INFINITY;
    int buf = 0;

    for (int c0 = s0; c0 < s1; c0 += 128, buf ^= 1) {
        const int cnt = min(128, s1 - c0);
        // dots: warp w -> local nodes w*8 .. w*8+7 (independent)
#pragma unroll
        for (int i = 0; i < 8; i++) {
            int nl = warp * 8 + i;
            if (nl < cnt) {
                const float* hr = hfeat + (size_t)(c0 + nl) * 256;
                float p = 0.f;
#pragma unroll
                for (int k = 0; k < 8; k++) p += hr[lane + 32 * k] * qreg[k];
#pragma unroll
                for (int off = 16; off; off >>= 1) p += __shfl_xor_sync(0xffffffffu, p, off);
                if (lane == 0) e_s[buf][nl] = p;
            }
        }
        __syncthreads();
        // all-warp redundant max (no extra sync)
        float v = -INFINITY;
#pragma unroll
        for (int j = 0; j < 4; j++) {
            int idx = lane + 32 * j;
            if (idx < cnt) v = fmaxf(v, e_s[buf][idx]);
        }
#pragma unroll
        for (int off = 16; off; off >>= 1)
            v = fmaxf(v, __shfl_xor_sync(0xffffffffu, v, off));
        const float mnew = fmaxf(m, v);
        const float scale = expf(m - mnew);
        acc *= scale; dpart *= scale; m = mnew;
        if (tid < cnt) {
            float wv = expf(e_s[buf][tid] - mnew);
            ws[buf][tid] = wv;
            dpart += wv;
        }
        __syncthreads();
        // weighted accumulation: half h -> local nodes [h*64, h*64+64)
        const int i0 = half * 64;
        const int i1 = min(cnt, i0 + 64);
        const float* bp = hfeat + ((size_t)c0 + i0) * 256 + col;
        const float* wp = ws[buf] + i0;
        if (i1 - i0 == 64) {
            float t0 = 0.f, t1 = 0.f, t2 = 0.f, t3 = 0.f;
#pragma unroll
            for (int i = 0; i < 64; i += 4) {
                t0 += wp[i]     * bp[(size_t)i * 256];
                t1 += wp[i + 1] * bp[(size_t)(i + 1) * 256];
                t2 += wp[i + 2] * bp[(size_t)(i + 2) * 256];
                t3 += wp[i + 3] * bp[(size_t)(i + 3) * 256];
            }
            acc += (t0 + t1) + (t2 + t3);
        } else {
            for (int i = 0; i < i1 - i0; i++) acc += wp[i] * bp[(size_t)i * 256];
        }
    }

    // denom reduce + combine halves
    float d = dpart;
#pragma unroll
    for (int off = 16; off; off >>= 1) d += __shfl_xor_sync(0xffffffffu, d, off);
    if (lane == 0) red[warp] = d;
    if (half == 0) racc[col] = acc;
    __syncthreads();
    if (tid == 0) {
        float s = 0.f;
        for (int i = 0; i < 16; i++) s += red[i];
        red[17] = s + 1e-16f;
    }
    __syncthreads();
    if (half == 1)
        qstar[b * 2 * H_ + 256 + col] = (racc[col] + acc) / red[17];
}

// ---------------- output projection ----------------
__global__ void k_out(const float* __restrict__ qstar, const float* __restrict__ W,
                      const float* __restrict__ bias, float* __restrict__ out)
{
    int b = blockIdx.x, e = threadIdx.x;
    __shared__ float qs[512];
    qs[e] = qstar[b * 512 + e];
    qs[e + 128] = qstar[b * 512 + e + 128];
    qs[e + 256] = qstar[b * 512 + e + 256];
    qs[e + 384] = qstar[b * 512 + e + 384];
    __syncthreads();
    float acc = bias[e];
#pragma unroll 8
    for (int k = 0; k < 512; k++) acc += qs[k] * W[k * E_ + e];
    out[b * E_ + e] = acc;
}

// ---------------- launch ----------------
extern "C" void kernel_launch(void* const* d_in, const int* in_sizes, int n_in,
                              void* d_out, int out_size)
{
    const float* x    = (const float*)d_in[0];
    const int*   bidx = (const int*)d_in[1];
    const float* W1   = (const float*)d_in[2];
    const float* b1   = (const float*)d_in[3];
    const float* W2   = (const float*)d_in[4];
    const float* b2   = (const float*)d_in[5];
    const float* Wih[3] = {(const float*)d_in[6],  (const float*)d_in[10], (const float*)d_in[14]};
    const float* Whh[3] = {(const float*)d_in[7],  (const float*)d_in[11], (const float*)d_in[15]};
    const float* bih[3] = {(const float*)d_in[8],  (const float*)d_in[12], (const float*)d_in[16]};
    const float* bhh[3] = {(const float*)d_in[9],  (const float*)d_in[13], (const float*)d_in[17]};
    const float* outW = (const float*)d_in[18];
    const float* outb = (const float*)d_in[19];
    float* out = (float*)d_out;

    const int N = in_sizes[0] / D_;

    float *tmp_p, *hfeat_p, *hbuf_p, *c_p, *qstar_p, *wt1_p, *wt2_p;
    cudaGetSymbolAddress((void**)&tmp_p,   g_tmp);
    cudaGetSymbolAddress((void**)&hfeat_p, g_hfeat);
    cudaGetSymbolAddress((void**)&hbuf_p,  g_hbuf);
    cudaGetSymbolAddress((void**)&c_p,     g_c);
    cudaGetSymbolAddress((void**)&qstar_p, g_qstar);
    cudaGetSymbolAddress((void**)&wt1_p,   g_Wt1);
    cudaGetSymbolAddress((void**)&wt2_p,   g_Wt2);

    cudaFuncSetAttribute(k_fnn_mma<true, true>,
                         cudaFuncAttributeMaxDynamicSharedMemorySize, SM_BYTES);
    cudaFuncSetAttribute(k_fnn_mma<false, false>,
                         cudaFuncAttributeMaxDynamicSharedMemorySize, SM_BYTES);

    k_init<<<256, 256>>>();
    k_seg<<<1, B_ + 1>>>(bidx, N);
    dim3 tb(32, 32);
    dim3 tg(8, 8, 2);
    k_transpose<<<tg, tb>>>(W1, W2, wt1_p, wt2_p);

    dim3 fg((N + 127) / 128, 2);
    k_fnn_mma<true, true ><<<fg, 256, SM_BYTES>>>(x,     wt1_p, b1, tmp_p,   N);
    k_fnn_mma<false, false><<<fg, 256, SM_BYTES>>>(tmp_p, wt2_p, b2, hfeat_p, N);

    dim3 lg(B_ / 32, H_ / 16);
    for (int s = 0; s < STEPS_; s++) {
        float* hold = hbuf_p + (size_t)(s & 1) * 3 * B_ * H_;
        float* hnew = hbuf_p + (size_t)((s & 1) ^ 1) * 3 * B_ * H_;
        for (int l = 0; l < 3; l++) {
            const float* xin = (l == 0) ? (const float*)qstar_p
                                        : (const float*)(hnew + (size_t)(l - 1) * B_ * H_);
            int KW = (l == 0) ? 2 * H_ : H_;
            k_lstm<<<lg, 256>>>(xin, KW, hold + (size_t)l * B_ * H_,
                                Wih[l], Whh[l], bih[l], bhh[l],
                                c_p + (size_t)l * B_ * H_,
                                hnew + (size_t)l * B_ * H_,
                                (l == 2) ? qstar_p : nullptr);
        }
        k_attn<<<B_, 512>>>(hfeat_p, hnew + (size_t)2 * B_ * H_, qstar_p);
    }
    k_out<<<B_, E_>>>(qstar_p, outW, outb, out);
}

// round 8
// speedup vs baseline: 1.6433x; 1.6433x over previous
#include <cuda_runtime.h>
#include <math.h>
#include <stdint.h>

#define D_ 256
#define H_ 256
#define B_ 128
#define E_ 128
#define STEPS_ 5
#define NMAX 100352
#define P_ 4            // attention partials per segment

// ---------------- scratch ----------------
__device__ __align__(16) float g_tmp[NMAX * H_];
__device__ __align__(16) float g_hfeat[NMAX * H_];
__device__ __align__(16) float g_gpart[2 * B_ * 4 * H_];
__device__ float g_hbuf[2][3][B_ * H_];
__device__ float g_c[3][B_ * H_];
__device__ float g_qstar[B_ * 2 * H_];
__device__ int   g_seg[B_ + 1];
__device__ __align__(16) float g_Wt1[D_ * H_];
__device__ __align__(16) float g_Wt2[H_ * H_];
__device__ float g_att_m[B_ * P_];
__device__ float g_att_d[B_ * P_];
__device__ __align__(16) float g_att_acc[B_ * P_ * H_];

__device__ __forceinline__ uint32_t cvt_tf32(float f) {
    uint32_t r;
    asm("cvt.rn.tf32.f32 %0, %1;" : "=r"(r) : "f"(f));
    return r;
}

// ---------------- init ----------------
__global__ void k_init() {
    int i = blockIdx.x * blockDim.x + threadIdx.x;
    int stride = gridDim.x * blockDim.x;
    for (int j = i; j < B_ * 2 * H_; j += stride) g_qstar[j] = 0.f;
    for (int j = i; j < 3 * B_ * H_; j += stride) {
        g_hbuf[0][0][j] = 0.f;
        g_hbuf[1][0][j] = 0.f;
        g_c[0][j] = 0.f;
    }
}

// ---------------- weight transpose + tf32 round ----------------
__global__ void k_transpose(const float* __restrict__ W1, const float* __restrict__ W2,
                            float* __restrict__ Wt1, float* __restrict__ Wt2) {
    __shared__ float t[32][33];
    const float* W  = blockIdx.z ? W2  : W1;
    float*       Wt = blockIdx.z ? Wt2 : Wt1;
    int bx = blockIdx.x * 32, by = blockIdx.y * 32;
    int tx = threadIdx.x, ty = threadIdx.y;
    t[ty][tx] = W[(by + ty) * 256 + bx + tx];
    __syncthreads();
    Wt[(bx + ty) * 256 + by + tx] = __uint_as_float(cvt_tf32(t[tx][ty]));
}

// ---------------- segment offsets ----------------
__global__ void k_seg(const int* __restrict__ idx, int N) {
    int b = threadIdx.x;
    if (b > B_) return;
    int lo = 0, hi = N;
    while (lo < hi) {
        int mid = (lo + hi) >> 1;
        if (idx[mid] < b) lo = mid + 1; else hi = mid;
    }
    g_seg[b] = lo;
}

// ---------------- FNN GEMM: tf32 HMMA, 3-stage cp.async, 2 CTA/SM ------------
#define KC 32
#define LDT 36
#define SM_STAGE (128 * LDT)
#define SM_BYTES (3 * 2 * SM_STAGE * 4)   // 110592 B

template <bool ELU, bool ROUND_OUT>
__global__ __launch_bounds__(256) void k_fnn_mma(
    const float* __restrict__ A, const float* __restrict__ Wt,
    const float* __restrict__ bias, float* __restrict__ C, int nrows)
{
    extern __shared__ float smem[];
    __shared__ float bias_s[128];

    const int tid  = threadIdx.x;
    const int lane = tid & 31;
    const int warp = tid >> 5;
    const int wm = warp >> 2;
    const int wn = warp & 3;
    const int row0 = blockIdx.x * 128;
    const int col0 = blockIdx.y * 128;

    if (tid < 128) bias_s[tid] = bias[col0 + tid];

    float acc[4][4][4];
#pragma unroll
    for (int mi = 0; mi < 4; mi++)
#pragma unroll
        for (int ni = 0; ni < 4; ni++)
#pragma unroll
            for (int j = 0; j < 4; j++) acc[mi][ni][j] = 0.f;

    const int qr = lane >> 2;
    const int qc = lane & 3;
    const int ldr = tid >> 3;
    const int ldq = (tid & 7) * 4;

    auto stage = [&](int kc, int s) {
        float* bufA = smem + s * 2 * SM_STAGE;
        float* bufB = bufA + SM_STAGE;
#pragma unroll
        for (int i = 0; i < 4; i++) {
            int r = ldr + 32 * i;
            int gr = row0 + r; if (gr >= nrows) gr = nrows - 1;
            uint32_t d = (uint32_t)__cvta_generic_to_shared(bufA + r * LDT + ldq);
            const float* sp = A + (size_t)gr * 256 + kc + ldq;
            asm volatile("cp.async.cg.shared.global [%0], [%1], 16;" :: "r"(d), "l"(sp) : "memory");
        }
#pragma unroll
        for (int i = 0; i < 4; i++) {
            int r = ldr + 32 * i;
            uint32_t d = (uint32_t)__cvta_generic_to_shared(bufB + r * LDT + ldq);
            const float* sp = Wt + (size_t)(col0 + r) * 256 + kc + ldq;
            asm volatile("cp.async.cg.shared.global [%0], [%1], 16;" :: "r"(d), "l"(sp) : "memory");
        }
        asm volatile("cp.async.commit_group;" ::: "memory");
    };

    stage(0, 0);
    stage(KC, 1);
    for (int c = 0; c < 8; c++) {
        if (c < 6) {
            stage((c + 2) * KC, (c + 2) % 3);
            asm volatile("cp.async.wait_group 2;" ::: "memory");
        } else if (c == 6) {
            asm volatile("cp.async.wait_group 1;" ::: "memory");
        } else {
            asm volatile("cp.async.wait_group 0;" ::: "memory");
        }
        __syncthreads();
        const float* As = smem + (c % 3) * 2 * SM_STAGE;
        const float* Bs = As + SM_STAGE;
#pragma unroll
        for (int ks = 0; ks < KC; ks += 8) {
            uint32_t af[4][4], bf[4][2];
#pragma unroll
            for (int mi = 0; mi < 4; mi++) {
                const float* ab = As + (wm * 64 + mi * 16) * LDT + ks;
                af[mi][0] = __float_as_uint(ab[qr * LDT + qc]);
                af[mi][1] = __float_as_uint(ab[(qr + 8) * LDT + qc]);
                af[mi][2] = __float_as_uint(ab[qr * LDT + qc + 4]);
                af[mi][3] = __float_as_uint(ab[(qr + 8) * LDT + qc + 4]);
            }
#pragma unroll
            for (int ni = 0; ni < 4; ni++) {
                const float* bb = Bs + (wn * 32 + ni * 8 + qr) * LDT + ks;
                bf[ni][0] = __float_as_uint(bb[qc]);
                bf[ni][1] = __float_as_uint(bb[qc + 4]);
            }
#pragma unroll
            for (int mi = 0; mi < 4; mi++)
#pragma unroll
                for (int ni = 0; ni < 4; ni++) {
                    asm volatile(
                        "mma.sync.aligned.m16n8k8.row.col.f32.tf32.tf32.f32 "
                        "{%0,%1,%2,%3}, {%4,%5,%6,%7}, {%8,%9}, {%0,%1,%2,%3};"
                        : "+f"(acc[mi][ni][0]), "+f"(acc[mi][ni][1]),
                          "+f"(acc[mi][ni][2]), "+f"(acc[mi][ni][3])
                        : "r"(af[mi][0]), "r"(af[mi][1]), "r"(af[mi][2]), "r"(af[mi][3]),
                          "r"(bf[ni][0]), "r"(bf[ni][1]));
                }
        }
        __syncthreads();
    }

#pragma unroll
    for (int mi = 0; mi < 4; mi++) {
        int r0 = row0 + wm * 64 + mi * 16 + qr;
#pragma unroll
        for (int ni = 0; ni < 4; ni++) {
            int cl = wn * 32 + ni * 8 + qc * 2;
            float b0 = bias_s[cl], b1 = bias_s[cl + 1];
            float v0 = acc[mi][ni][0] + b0, v1 = acc[mi][ni][1] + b1;
            float v2 = acc[mi][ni][2] + b0, v3 = acc[mi][ni][3] + b1;
            if (ELU) {
                v0 = (v0 > 0.f) ? v0 : expm1f(v0);
                v1 = (v1 > 0.f) ? v1 : expm1f(v1);
                v2 = (v2 > 0.f) ? v2 : expm1f(v2);
                v3 = (v3 > 0.f) ? v3 : expm1f(v3);
            }
            if (ROUND_OUT) {
                v0 = __uint_as_float(cvt_tf32(v0));
                v1 = __uint_as_float(cvt_tf32(v1));
                v2 = __uint_as_float(cvt_tf32(v2));
                v3 = __uint_as_float(cvt_tf32(v3));
            }
            int cg = col0 + cl;
            if (r0 < nrows)
                *(float2*)(C + (size_t)r0 * 256 + cg) = make_float2(v0, v1);
            if (r0 + 8 < nrows)
                *(float2*)(C + (size_t)(r0 + 8) * 256 + cg) = make_float2(v2, v3);
        }
    }
}

// ---------------- LSTM gates GEMM (fp32, split-K=2) — known good -------------
__global__ __launch_bounds__(256) void k_gates(
    const float* __restrict__ xin, int KW,
    const float* __restrict__ hold,
    const float* __restrict__ Wih, const float* __restrict__ Whh,
    float* __restrict__ gpart)
{
    __shared__ float a_s[32][33];
    __shared__ float w_s[32][33];
    const int tid = threadIdx.x;
    const int b0 = blockIdx.x * 32, j0 = blockIdx.y * 32;
    const int KT = KW + H_;
    const int khalf = KT >> 1;
    const int kbeg = blockIdx.z * khalf, kend = kbeg + khalf;
    const int ty = tid >> 4, tx = tid & 15;
    const int lr = tid >> 3, lc = (tid & 7) * 4;
    float a00 = 0.f, a01 = 0.f, a10 = 0.f, a11 = 0.f;

    for (int kt = kbeg; kt < kend; kt += 32) {
        const float *As, *Ws; int k, str;
        if (kt < KW) { As = xin;  Ws = Wih; k = kt;      str = KW; }
        else         { As = hold; Ws = Whh; k = kt - KW; str = H_; }
        float4 av = *(const float4*)(As + (size_t)(b0 + lr) * str + k + lc);
        a_s[lr][lc + 0] = av.x; a_s[lr][lc + 1] = av.y;
        a_s[lr][lc + 2] = av.z; a_s[lr][lc + 3] = av.w;
        float4 wv = *(const float4*)(Ws + (size_t)(j0 + lr) * str + k + lc);
        w_s[lr][lc + 0] = wv.x; w_s[lr][lc + 1] = wv.y;
        w_s[lr][lc + 2] = wv.z; w_s[lr][lc + 3] = wv.w;
        __syncthreads();
#pragma unroll
        for (int kk = 0; kk < 32; kk++) {
            float x0 = a_s[ty][kk], x1 = a_s[ty + 16][kk];
            float w0 = w_s[tx][kk], w1 = w_s[tx + 16][kk];
            a00 += x0 * w0; a01 += x0 * w1;
            a10 += x1 * w0; a11 += x1 * w1;
        }
        __syncthreads();
    }
    float* gp = gpart + (size_t)blockIdx.z * (B_ * 4 * H_);
    gp[(size_t)(b0 + ty)      * 1024 + j0 + tx]      = a00;
    gp[(size_t)(b0 + ty)      * 1024 + j0 + tx + 16] = a01;
    gp[(size_t)(b0 + ty + 16) * 1024 + j0 + tx]      = a10;
    gp[(size_t)(b0 + ty + 16) * 1024 + j0 + tx + 16] = a11;
}

// ---------------- LSTM cell elementwise ----------------
__device__ __forceinline__ float sigf(float x) { return 1.f / (1.f + expf(-x)); }

__global__ void k_update(const float* __restrict__ gp0, const float* __restrict__ gp1,
                         const float* __restrict__ bih, const float* __restrict__ bhh,
                         float* __restrict__ c, float* __restrict__ hnew,
                         float* __restrict__ qdst)
{
    int b = blockIdx.x, j = threadIdx.x;
    size_t g0 = (size_t)b * 1024;
    float iv = gp0[g0 + j]       + gp1[g0 + j]       + bih[j]       + bhh[j];
    float fv = gp0[g0 + 256 + j] + gp1[g0 + 256 + j] + bih[256 + j] + bhh[256 + j];
    float gv = gp0[g0 + 512 + j] + gp1[g0 + 512 + j] + bih[512 + j] + bhh[512 + j];
    float ov = gp0[g0 + 768 + j] + gp1[g0 + 768 + j] + bih[768 + j] + bhh[768 + j];
    float cn = sigf(fv) * c[b * H_ + j] + sigf(iv) * tanhf(gv);
    c[b * H_ + j] = cn;
    float hn = sigf(ov) * tanhf(cn);
    hnew[b * H_ + j] = hn;
    if (qdst) qdst[b * 2 * H_ + j] = hn;
}

// ---------------- attention partials: grid (B, P_), online softmax -----------
__global__ __launch_bounds__(512) void k_attn_part(
    const float* __restrict__ hfeat, const float* __restrict__ q)
{
    const int b = blockIdx.x, part = blockIdx.y, tid = threadIdx.x;
    const int g0 = g_seg[b], g1 = g_seg[b + 1];
    const int len = g1 - g0;
    const int s0 = g0 + (int)(((long long)len * part) / P_);
    const int s1 = g0 + (int)(((long long)len * (part + 1)) / P_);

    __shared__ float q_s[256];
    __shared__ float e_s[2][128];
    __shared__ float ws[2][128];
    __shared__ float racc[256];
    __shared__ float red[16];
    if (tid < 256) q_s[tid] = q[b * 256 + tid];
    __syncthreads();

    const int lane = tid & 31, warp = tid >> 5;
    const int col = tid & 255, half = tid >> 8;
    float qreg[8];
#pragma unroll
    for (int k = 0; k < 8; k++) qreg[k] = q_s[lane + 32 * k];

    float acc = 0.f, dpart = 0.f, m = -INFINITY;
    int buf = 0;

    for (int c0 = s0; c0 < s1; c0 += 128, buf ^= 1) {
        const int cnt = min(128, s1 - c0);
#pragma unroll
        for (int i = 0; i < 8; i++) {
            int nl = warp * 8 + i;
            if (nl < cnt) {
                const float* hr = hfeat + (size_t)(c0 + nl) * 256;
                float p = 0.f;
#pragma unroll
                for (int k = 0; k < 8; k++) p += hr[lane + 32 * k] * qreg[k];
#pragma unroll
                for (int off = 16; off; off >>= 1) p += __shfl_xor_sync(0xffffffffu, p, off);
                if (lane == 0) e_s[buf][nl] = p;
            }
        }
        __syncthreads();
        float v = -INFINITY;
#pragma unroll
        for (int j = 0; j < 4; j++) {
            int idx = lane + 32 * j;
            if (idx < cnt) v = fmaxf(v, e_s[buf][idx]);
        }
#pragma unroll
        for (int off = 16; off; off >>= 1)
            v = fmaxf(v, __shfl_xor_sync(0xffffffffu, v, off));
        const float mnew = fmaxf(m, v);
        const float scale = expf(m - mnew);
        acc *= scale; dpart *= scale; m = mnew;
        if (tid < cnt) {
            float wv = expf(e_s[buf][tid] - mnew);
            ws[buf][tid] = wv;
            dpart += wv;
        }
        __syncthreads();
        const int i0 = half * 64;
        const int i1 = min(cnt, i0 + 64);
        const float* bp = hfeat + ((size_t)c0 + i0) * 256 + col;
        const float* wp = ws[buf] + i0;
        if (i1 - i0 == 64) {
            float t0 = 0.f, t1 = 0.f, t2 = 0.f, t3 = 0.f;
#pragma unroll
            for (int i = 0; i < 64; i += 4) {
                t0 += wp[i]     * bp[(size_t)i * 256];
                t1 += wp[i + 1] * bp[(size_t)(i + 1) * 256];
                t2 += wp[i + 2] * bp[(size_t)(i + 2) * 256];
                t3 += wp[i + 3] * bp[(size_t)(i + 3) * 256];
            }
            acc += (t0 + t1) + (t2 + t3);
        } else {
            for (int i = 0; i < i1 - i0; i++) acc += wp[i] * bp[(size_t)i * 256];
        }
    }

    float d = dpart;
#pragma unroll
    for (int off = 16; off; off >>= 1) d += __shfl_xor_sync(0xffffffffu, d, off);
    if (lane == 0) red[warp] = d;
    if (half == 0) racc[col] = acc;
    __syncthreads();
    const int idx = b * P_ + part;
    if (tid == 0) {
        float s = 0.f;
        for (int i = 0; i < 16; i++) s += red[i];
        g_att_d[idx] = s;
        g_att_m[idx] = m;
    }
    if (half == 1) g_att_acc[(size_t)idx * 256 + col] = racc[col] + acc;
}

// ---------------- attention combine: merge P_ partials per segment -----------
__global__ __launch_bounds__(256) void k_attn_comb(float* __restrict__ qstar)
{
    const int b = blockIdx.x, col = threadIdx.x;
    __shared__ float sc[P_];
    __shared__ float sdenom;
    if (col == 0) {
        float m = -INFINITY;
#pragma unroll
        for (int p = 0; p < P_; p++) m = fmaxf(m, g_att_m[b * P_ + p]);
        if (!isfinite(m)) m = 0.f;
        float denom = 0.f;
#pragma unroll
        for (int p = 0; p < P_; p++) {
            float e = expf(g_att_m[b * P_ + p] - m);   // exp(-inf)=0 for empty parts
            sc[p] = e;
            denom += g_att_d[b * P_ + p] * e;
        }
        sdenom = denom + 1e-16f;
    }
    __syncthreads();
    float r = 0.f;
#pragma unroll
    for (int p = 0; p < P_; p++)
        r += sc[p] * g_att_acc[(size_t)(b * P_ + p) * 256 + col];
    qstar[b * 2 * H_ + 256 + col] = r / sdenom;
}

// ---------------- output projection ----------------
__global__ void k_out(const float* __restrict__ qstar, const float* __restrict__ W,
                      const float* __restrict__ bias, float* __restrict__ out)
{
    int b = blockIdx.x, e = threadIdx.x;
    __shared__ float qs[512];
    qs[e] = qstar[b * 512 + e];
    qs[e + 128] = qstar[b * 512 + e + 128];
    qs[e + 256] = qstar[b * 512 + e + 256];
    qs[e + 384] = qstar[b * 512 + e + 384];
    __syncthreads();
    float acc = bias[e];
#pragma unroll 8
    for (int k = 0; k < 512; k++) acc += qs[k] * W[k * E_ + e];
    out[b * E_ + e] = acc;
}

// ---------------- launch ----------------
extern "C" void kernel_launch(void* const* d_in, const int* in_sizes, int n_in,
                              void* d_out, int out_size)
{
    const float* x    = (const float*)d_in[0];
    const int*   bidx = (const int*)d_in[1];
    const float* W1   = (const float*)d_in[2];
    const float* b1   = (const float*)d_in[3];
    const float* W2   = (const float*)d_in[4];
    const float* b2   = (const float*)d_in[5];
    const float* Wih[3] = {(const float*)d_in[6],  (const float*)d_in[10], (const float*)d_in[14]};
    const float* Whh[3] = {(const float*)d_in[7],  (const float*)d_in[11], (const float*)d_in[15]};
    const float* bih[3] = {(const float*)d_in[8],  (const float*)d_in[12], (const float*)d_in[16]};
    const float* bhh[3] = {(const float*)d_in[9],  (const float*)d_in[13], (const float*)d_in[17]};
    const float* outW = (const float*)d_in[18];
    const float* outb = (const float*)d_in[19];
    float* out = (float*)d_out;

    const int N = in_sizes[0] / D_;

    float *tmp_p, *hfeat_p, *gpart_p, *hbuf_p, *c_p, *qstar_p, *wt1_p, *wt2_p;
    cudaGetSymbolAddress((void**)&tmp_p,   g_tmp);
    cudaGetSymbolAddress((void**)&hfeat_p, g_hfeat);
    cudaGetSymbolAddress((void**)&gpart_p, g_gpart);
    cudaGetSymbolAddress((void**)&hbuf_p,  g_hbuf);
    cudaGetSymbolAddress((void**)&c_p,     g_c);
    cudaGetSymbolAddress((void**)&qstar_p, g_qstar);
    cudaGetSymbolAddress((void**)&wt1_p,   g_Wt1);
    cudaGetSymbolAddress((void**)&wt2_p,   g_Wt2);

    cudaFuncSetAttribute(k_fnn_mma<true, true>,
                         cudaFuncAttributeMaxDynamicSharedMemorySize, SM_BYTES);
    cudaFuncSetAttribute(k_fnn_mma<false, false>,
                         cudaFuncAttributeMaxDynamicSharedMemorySize, SM_BYTES);

    k_init<<<256, 256>>>();
    k_seg<<<1, B_ + 1>>>(bidx, N);
    dim3 tb(32, 32);
    dim3 tg(8, 8, 2);
    k_transpose<<<tg, tb>>>(W1, W2, wt1_p, wt2_p);

    dim3 fg((N + 127) / 128, 2);
    k_fnn_mma<true, true ><<<fg, 256, SM_BYTES>>>(x,     wt1_p, b1, tmp_p,   N);
    k_fnn_mma<false, false><<<fg, 256, SM_BYTES>>>(tmp_p, wt2_p, b2, hfeat_p, N);

    for (int s = 0; s < STEPS_; s++) {
        float* hold = hbuf_p + (size_t)(s & 1) * 3 * B_ * H_;
        float* hnew = hbuf_p + (size_t)((s & 1) ^ 1) * 3 * B_ * H_;
        for (int l = 0; l < 3; l++) {
            const float* xin = (l == 0) ? (const float*)qstar_p
                                        : (const float*)(hnew + (size_t)(l - 1) * B_ * H_);
            int KW = (l == 0) ? 2 * H_ : H_;
            dim3 gg(B_ / 32, 4 * H_ / 32, 2);
            k_gates<<<gg, 256>>>(xin, KW, hold + (size_t)l * B_ * H_,
                                 Wih[l], Whh[l], gpart_p);
            k_update<<<B_, H_>>>(gpart_p, gpart_p + (size_t)B_ * 4 * H_,
                                 bih[l], bhh[l],
                                 c_p + (size_t)l * B_ * H_,
                                 hnew + (size_t)l * B_ * H_,
                                 (l == 2) ? qstar_p : nullptr);
        }
        dim3 ag(B_, P_);
        k_attn_part<<<ag, 512>>>(hfeat_p, hnew + (size_t)2 * B_ * H_);
        k_attn_comb<<<B_, 256>>>(qstar_p);
    }
    k_out<<<B_, E_>>>(qstar_p, outW, outb, out);
}

// round 9
// speedup vs baseline: 1.6950x; 1.0314x over previous
#include <cuda_runtime.h>
#include <math.h>
#include <stdint.h>

#define D_ 256
#define H_ 256
#define B_ 128
#define E_ 128
#define STEPS_ 5
#define NMAX 100352
#define P_ 8            // attention partials per segment

// ---------------- scratch ----------------
__device__ __align__(16) float g_hfeat[NMAX * H_];
__device__ __align__(16) float g_gpart[2 * B_ * 4 * H_];
__device__ float g_hbuf[2][3][B_ * H_];
__device__ float g_c[3][B_ * H_];
__device__ float g_qstar[B_ * 2 * H_];
__device__ int   g_seg[B_ + 1];
__device__ __align__(16) float g_Wt1[D_ * H_];
__device__ __align__(16) float g_Wt2[H_ * H_];
__device__ float g_att_m[B_ * P_];
__device__ float g_att_d[B_ * P_];
__device__ __align__(16) float g_att_acc[B_ * P_ * H_];

__device__ __forceinline__ uint32_t cvt_tf32(float f) {
    uint32_t r;
    asm("cvt.rn.tf32.f32 %0, %1;" : "=r"(r) : "f"(f));
    return r;
}

// ---------------- init ----------------
__global__ void k_init() {
    int i = blockIdx.x * blockDim.x + threadIdx.x;
    int stride = gridDim.x * blockDim.x;
    for (int j = i; j < B_ * 2 * H_; j += stride) g_qstar[j] = 0.f;
    for (int j = i; j < 3 * B_ * H_; j += stride) {
        g_hbuf[0][0][j] = 0.f;
        g_hbuf[1][0][j] = 0.f;
        g_c[0][j] = 0.f;
    }
}

// ---------------- weight transpose + tf32 round ----------------
__global__ void k_transpose(const float* __restrict__ W1, const float* __restrict__ W2,
                            float* __restrict__ Wt1, float* __restrict__ Wt2) {
    __shared__ float t[32][33];
    const float* W  = blockIdx.z ? W2  : W1;
    float*       Wt = blockIdx.z ? Wt2 : Wt1;
    int bx = blockIdx.x * 32, by = blockIdx.y * 32;
    int tx = threadIdx.x, ty = threadIdx.y;
    t[ty][tx] = W[(by + ty) * 256 + bx + tx];
    __syncthreads();
    Wt[(bx + ty) * 256 + by + tx] = __uint_as_float(cvt_tf32(t[tx][ty]));
}

// ---------------- segment offsets ----------------
__global__ void k_seg(const int* __restrict__ idx, int N) {
    int b = threadIdx.x;
    if (b > B_) return;
    int lo = 0, hi = N;
    while (lo < hi) {
        int mid = (lo + hi) >> 1;
        if (idx[mid] < b) lo = mid + 1; else hi = mid;
    }
    g_seg[b] = lo;
}

// ---------------- fused FNN: GEMM1 -> ELU -> h(smem) -> GEMM2 ----------------
// 512 threads = 16 warps (wm=warp&3: 4 x 32 rows; wn=warp>>2: 4 x 64 cols).
// Warp tile 32x64, per-thread acc[2][8][4]. XOR-swizzled smem (conflict-free).
#define FH 0
#define FSA 131072
#define FSB 163840
#define FSMEM 229376

#define CP16(dst, src) \
    asm volatile("cp.async.cg.shared.global [%0], [%1], 16;" :: "r"(dst), "l"(src) : "memory")
#define CPCOMMIT() asm volatile("cp.async.commit_group;" ::: "memory")
#define CPWAIT(n)  asm volatile("cp.async.wait_group %0;" :: "n"(n) : "memory")

#define MMA_TF32(d, a, b) \
    asm volatile( \
        "mma.sync.aligned.m16n8k8.row.col.f32.tf32.tf32.f32 " \
        "{%0,%1,%2,%3}, {%4,%5,%6,%7}, {%8,%9}, {%0,%1,%2,%3};" \
        : "+f"((d)[0]), "+f"((d)[1]), "+f"((d)[2]), "+f"((d)[3]) \
        : "r"((a)[0]), "r"((a)[1]), "r"((a)[2]), "r"((a)[3]), \
          "r"((b)[0]), "r"((b)[1]))

__global__ __launch_bounds__(512) void k_fnn_fused(
    const float* __restrict__ X, const float* __restrict__ W1t,
    const float* __restrict__ W2t, const float* __restrict__ b1,
    const float* __restrict__ b2, float* __restrict__ Cout, int nrows)
{
    extern __shared__ char sm[];
    float* hbuf = (float*)(sm + FH);             // [128][256] swizzled
    __shared__ float bias1[256];
    __shared__ float bias2[256];

    const int tid  = threadIdx.x;
    const int lane = tid & 31;
    const int warp = tid >> 5;
    const int wm = warp & 3;       // m-slab (32 rows)
    const int wn = warp >> 2;      // n-slab (64 cols)
    const int qr = lane >> 2;
    const int qc = lane & 3;
    const int row0 = blockIdx.x * 128;

    if (tid < 256) bias1[tid] = b1[tid];
    else           bias2[tid - 256] = b2[tid - 256];

    float acc[2][8][4];
#pragma unroll
    for (int mi = 0; mi < 2; mi++)
#pragma unroll
        for (int ni = 0; ni < 8; ni++)
#pragma unroll
            for (int j = 0; j < 4; j++) acc[mi][ni][j] = 0.f;

    // ---- phase 1: h = ELU(X @ W1t^T + b1), staged A+B, 2-buffer ----
    auto stage1 = [&](int kc, int s) {
        char* dA = sm + FSA + s * 16384;
        char* dB = sm + FSB + s * 32768;
#pragma unroll
        for (int i = 0; i < 2; i++) {
            int gid = tid + 512 * i;
            int r = gid >> 3, g = gid & 7;
            int gr = row0 + r; if (gr >= nrows) gr = nrows - 1;
            uint32_t dst = (uint32_t)__cvta_generic_to_shared(
                dA + r * 128 + ((g ^ (r & 7)) << 4));
            CP16(dst, X + (size_t)gr * 256 + kc + g * 4);
        }
#pragma unroll
        for (int i = 0; i < 4; i++) {
            int gid = tid + 512 * i;
            int r = gid >> 3, g = gid & 7;
            uint32_t dst = (uint32_t)__cvta_generic_to_shared(
                dB + r * 128 + ((g ^ (r & 7)) << 4));
            CP16(dst, W1t + (size_t)r * 256 + kc + g * 4);
        }
        CPCOMMIT();
    };

    stage1(0, 0);
    for (int c = 0; c < 8; c++) {
        if (c + 1 < 8) { stage1((c + 1) * 32, (c + 1) & 1); CPWAIT(1); }
        else           { CPWAIT(0); }
        __syncthreads();
        const float* As = (const float*)(sm + FSA + (c & 1) * 16384);
        const float* Bs = (const float*)(sm + FSB + (c & 1) * 32768);
#pragma unroll
        for (int ks = 0; ks < 32; ks += 8) {
            const int g0 = ks >> 2;
            uint32_t af[2][4], bf[8][2];
#pragma unroll
            for (int mi = 0; mi < 2; mi++) {
                int ra = wm * 32 + mi * 16 + qr;
                int sw = (ra & 7);
                const float* pa  = As + ra * 32;
                const float* pa8 = pa + 8 * 32;
                af[mi][0] = __float_as_uint(pa [((g0 ^ sw) << 2) + qc]);
                af[mi][1] = __float_as_uint(pa8[((g0 ^ sw) << 2) + qc]);
                af[mi][2] = __float_as_uint(pa [(((g0 + 1) ^ sw) << 2) + qc]);
                af[mi][3] = __float_as_uint(pa8[(((g0 + 1) ^ sw) << 2) + qc]);
            }
#pragma unroll
            for (int ni = 0; ni < 8; ni++) {
                int rb = wn * 64 + ni * 8 + qr;
                int sw = (rb & 7);
                const float* pb = Bs + rb * 32;
                bf[ni][0] = __float_as_uint(pb[((g0 ^ sw) << 2) + qc]);
                bf[ni][1] = __float_as_uint(pb[(((g0 + 1) ^ sw) << 2) + qc]);
            }
#pragma unroll
            for (int mi = 0; mi < 2; mi++)
#pragma unroll
                for (int ni = 0; ni < 8; ni++) MMA_TF32(acc[mi][ni], af[mi], bf[ni]);
        }
        __syncthreads();
    }

    // ---- phase-1 epilogue: bias + ELU + tf32 round -> swizzled h in smem ----
#pragma unroll
    for (int mi = 0; mi < 2; mi++) {
        int r = wm * 32 + mi * 16 + qr;
        int sw = (r & 7);               // (r+8)&7 == r&7
#pragma unroll
        for (int ni = 0; ni < 8; ni++) {
            int cb = wn * 64 + ni * 8 + qc * 2;
            float b0 = bias1[cb], b1v = bias1[cb + 1];
            float v0 = acc[mi][ni][0] + b0, v1 = acc[mi][ni][1] + b1v;
            float v2 = acc[mi][ni][2] + b0, v3 = acc[mi][ni][3] + b1v;
            v0 = (v0 > 0.f) ? v0 : expm1f(v0);
            v1 = (v1 > 0.f) ? v1 : expm1f(v1);
            v2 = (v2 > 0.f) ? v2 : expm1f(v2);
            v3 = (v3 > 0.f) ? v3 : expm1f(v3);
            int gg = cb >> 2, go = cb & 3;
            float* hp  = hbuf + r * 256 + ((gg ^ sw) << 2) + go;
            float* hp8 = hp + 8 * 256;
            hp [0] = __uint_as_float(cvt_tf32(v0));
            hp [1] = __uint_as_float(cvt_tf32(v1));
            hp8[0] = __uint_as_float(cvt_tf32(v2));
            hp8[1] = __uint_as_float(cvt_tf32(v3));
            acc[mi][ni][0] = 0.f; acc[mi][ni][1] = 0.f;
            acc[mi][ni][2] = 0.f; acc[mi][ni][3] = 0.f;
        }
    }
    __syncthreads();

    // ---- phase 2: out = h @ W2t^T + b2, A from smem h, B staged ----
    auto stage2 = [&](int kc, int s) {
        char* dB = sm + FSB + s * 32768;
#pragma unroll
        for (int i = 0; i < 4; i++) {
            int gid = tid + 512 * i;
            int r = gid >> 3, g = gid & 7;
            uint32_t dst = (uint32_t)__cvta_generic_to_shared(
                dB + r * 128 + ((g ^ (r & 7)) << 4));
            CP16(dst, W2t + (size_t)r * 256 + kc + g * 4);
        }
        CPCOMMIT();
    };

    stage2(0, 0);
    for (int c = 0; c < 8; c++) {
        if (c + 1 < 8) { stage2((c + 1) * 32, (c + 1) & 1); CPWAIT(1); }
        else           { CPWAIT(0); }
        __syncthreads();
        const float* Bs = (const float*)(sm + FSB + (c & 1) * 32768);
#pragma unroll
        for (int ks = 0; ks < 32; ks += 8) {
            const int g0 = (c * 32 + ks) >> 2;   // h granule (0..63)
            const int g0l = ks >> 2;             // staged-B granule (0..7)
            uint32_t af[2][4], bf[8][2];
#pragma unroll
            for (int mi = 0; mi < 2; mi++) {
                int ra = wm * 32 + mi * 16 + qr;
                int sw = (ra & 7);
                const float* pa  = hbuf + ra * 256;
                const float* pa8 = pa + 8 * 256;
                af[mi][0] = __float_as_uint(pa [((g0 ^ sw) << 2) + qc]);
                af[mi][1] = __float_as_uint(pa8[((g0 ^ sw) << 2) + qc]);
                af[mi][2] = __float_as_uint(pa [(((g0 + 1) ^ sw) << 2) + qc]);
                af[mi][3] = __float_as_uint(pa8[(((g0 + 1) ^ sw) << 2) + qc]);
            }
#pragma unroll
            for (int ni = 0; ni < 8; ni++) {
                int rb = wn * 64 + ni * 8 + qr;
                int sw = (rb & 7);
                const float* pb = Bs + rb * 32;
                bf[ni][0] = __float_as_uint(pb[((g0l ^ sw) << 2) + qc]);
                bf[ni][1] = __float_as_uint(pb[(((g0l + 1) ^ sw) << 2) + qc]);
            }
#pragma unroll
            for (int mi = 0; mi < 2; mi++)
#pragma unroll
                for (int ni = 0; ni < 8; ni++) MMA_TF32(acc[mi][ni], af[mi], bf[ni]);
        }
        __syncthreads();
    }

    // ---- phase-2 epilogue: bias + store to gmem ----
#pragma unroll
    for (int mi = 0; mi < 2; mi++) {
        int r0 = row0 + wm * 32 + mi * 16 + qr;
#pragma unroll
        for (int ni = 0; ni < 8; ni++) {
            int cb = wn * 64 + ni * 8 + qc * 2;
            float b0 = bias2[cb], b1v = bias2[cb + 1];
            if (r0 < nrows)
                *(float2*)(Cout + (size_t)r0 * 256 + cb) =
                    make_float2(acc[mi][ni][0] + b0, acc[mi][ni][1] + b1v);
            if (r0 + 8 < nrows)
                *(float2*)(Cout + (size_t)(r0 + 8) * 256 + cb) =
                    make_float2(acc[mi][ni][2] + b0, acc[mi][ni][3] + b1v);
        }
    }
}

// ---------------- LSTM gates GEMM (fp32, split-K=2) — known good -------------
__global__ __launch_bounds__(256) void k_gates(
    const float* __restrict__ xin, int KW,
    const float* __restrict__ hold,
    const float* __restrict__ Wih, const float* __restrict__ Whh,
    float* __restrict__ gpart)
{
    __shared__ float a_s[32][33];
    __shared__ float w_s[32][33];
    const int tid = threadIdx.x;
    const int b0 = blockIdx.x * 32, j0 = blockIdx.y * 32;
    const int KT = KW + H_;
    const int khalf = KT >> 1;
    const int kbeg = blockIdx.z * khalf, kend = kbeg + khalf;
    const int ty = tid >> 4, tx = tid & 15;
    const int lr = tid >> 3, lc = (tid & 7) * 4;
    float a00 = 0.f, a01 = 0.f, a10 = 0.f, a11 = 0.f;

    for (int kt = kbeg; kt < kend; kt += 32) {
        const float *As, *Ws; int k, str;
        if (kt < KW) { As = xin;  Ws = Wih; k = kt;      str = KW; }
        else         { As = hold; Ws = Whh; k = kt - KW; str = H_; }
        float4 av = *(const float4*)(As + (size_t)(b0 + lr) * str + k + lc);
        a_s[lr][lc + 0] = av.x; a_s[lr][lc + 1] = av.y;
        a_s[lr][lc + 2] = av.z; a_s[lr][lc + 3] = av.w;
        float4 wv = *(const float4*)(Ws + (size_t)(j0 + lr) * str + k + lc);
        w_s[lr][lc + 0] = wv.x; w_s[lr][lc + 1] = wv.y;
        w_s[lr][lc + 2] = wv.z; w_s[lr][lc + 3] = wv.w;
        __syncthreads();
#pragma unroll
        for (int kk = 0; kk < 32; kk++) {
            float x0 = a_s[ty][kk], x1 = a_s[ty + 16][kk];
            float w0 = w_s[tx][kk], w1 = w_s[tx + 16][kk];
            a00 += x0 * w0; a01 += x0 * w1;
            a10 += x1 * w0; a11 += x1 * w1;
        }
        __syncthreads();
    }
    float* gp = gpart + (size_t)blockIdx.z * (B_ * 4 * H_);
    gp[(size_t)(b0 + ty)      * 1024 + j0 + tx]      = a00;
    gp[(size_t)(b0 + ty)      * 1024 + j0 + tx + 16] = a01;
    gp[(size_t)(b0 + ty + 16) * 1024 + j0 + tx]      = a10;
    gp[(size_t)(b0 + ty + 16) * 1024 + j0 + tx + 16] = a11;
}

// ---------------- LSTM cell elementwise ----------------
__device__ __forceinline__ float sigf(float x) { return 1.f / (1.f + expf(-x)); }

__global__ void k_update(const float* __restrict__ gp0, const float* __restrict__ gp1,
                         const float* __restrict__ bih, const float* __restrict__ bhh,
                         float* __restrict__ c, float* __restrict__ hnew,
                         float* __restrict__ qdst)
{
    int b = blockIdx.x, j = threadIdx.x;
    size_t g0 = (size_t)b * 1024;
    float iv = gp0[g0 + j]       + gp1[g0 + j]       + bih[j]       + bhh[j];
    float fv = gp0[g0 + 256 + j] + gp1[g0 + 256 + j] + bih[256 + j] + bhh[256 + j];
    float gv = gp0[g0 + 512 + j] + gp1[g0 + 512 + j] + bih[512 + j] + bhh[512 + j];
    float ov = gp0[g0 + 768 + j] + gp1[g0 + 768 + j] + bih[768 + j] + bhh[768 + j];
    float cn = sigf(fv) * c[b * H_ + j] + sigf(iv) * tanhf(gv);
    c[b * H_ + j] = cn;
    float hn = sigf(ov) * tanhf(cn);
    hnew[b * H_ + j] = hn;
    if (qdst) qdst[b * 2 * H_ + j] = hn;
}

// ---------------- attention partials: grid (B, P_), online softmax -----------
__global__ __launch_bounds__(512) void k_attn_part(
    const float* __restrict__ hfeat, const float* __restrict__ q)
{
    const int b = blockIdx.x, part = blockIdx.y, tid = threadIdx.x;
    const int g0 = g_seg[b], g1 = g_seg[b + 1];
    const int len = g1 - g0;
    const int s0 = g0 + (int)(((long long)len * part) / P_);
    const int s1 = g0 + (int)(((long long)len * (part + 1)) / P_);

    __shared__ float q_s[256];
    __shared__ float e_s[2][128];
    __shared__ float ws[2][128];
    __shared__ float racc[256];
    __shared__ float red[16];
    if (tid < 256) q_s[tid] = q[b * 256 + tid];
    __syncthreads();

    const int lane = tid & 31, warp = tid >> 5;
    const int col = tid & 255, half = tid >> 8;
    float qreg[8];
#pragma unroll
    for (int k = 0; k < 8; k++) qreg[k] = q_s[lane + 32 * k];

    float acc = 0.f, dpart = 0.f, m = -INFINITY;
    int buf = 0;

    for (int c0 = s0; c0 < s1; c0 += 128, buf ^= 1) {
        const int cnt = min(128, s1 - c0);
#pragma unroll
        for (int i = 0; i < 8; i++) {
            int nl = warp * 8 + i;
            if (nl < cnt) {
                const float* hr = hfeat + (size_t)(c0 + nl) * 256;
                float p = 0.f;
#pragma unroll
                for (int k = 0; k < 8; k++) p += hr[lane + 32 * k] * qreg[k];
#pragma unroll
                for (int off = 16; off; off >>= 1) p += __shfl_xor_sync(0xffffffffu, p, off);
                if (lane == 0) e_s[buf][nl] = p;
            }
        }
        __syncthreads();
        float v = -INFINITY;
#pragma unroll
        for (int j = 0; j < 4; j++) {
            int idx = lane + 32 * j;
            if (idx < cnt) v = fmaxf(v, e_s[buf][idx]);
        }
#pragma unroll
        for (int off = 16; off; off >>= 1)
            v = fmaxf(v, __shfl_xor_sync(0xffffffffu, v, off));
        const float mnew = fmaxf(m, v);
        const float scale = expf(m - mnew);
        acc *= scale; dpart *= scale; m = mnew;
        if (tid < cnt) {
            float wv = expf(e_s[buf][tid] - mnew);
            ws[buf][tid] = wv;
            dpart += wv;
        }
        __syncthreads();
        const int i0 = half * 64;
        const int i1 = min(cnt, i0 + 64);
        const float* bp = hfeat + ((size_t)c0 + i0) * 256 + col;
        const float* wp = ws[buf] + i0;
        if (i1 - i0 == 64) {
            float t0 = 0.f, t1 = 0.f, t2 = 0.f, t3 = 0.f;
#pragma unroll
            for (int i = 0; i < 64; i += 4) {
                t0 += wp[i]     * bp[(size_t)i * 256];
                t1 += wp[i + 1] * bp[(size_t)(i + 1) * 256];
                t2 += wp[i + 2] * bp[(size_t)(i + 2) * 256];
                t3 += wp[i + 3] * bp[(size_t)(i + 3) * 256];
            }
            acc += (t0 + t1) + (t2 + t3);
        } else {
            for (int i = 0; i < i1 - i0; i++) acc += wp[i] * bp[(size_t)i * 256];
        }
    }

    float d = dpart;
#pragma unroll
    for (int off = 16; off; off >>= 1) d += __shfl_xor_sync(0xffffffffu, d, off);
    if (lane == 0) red[warp] = d;
    if (half == 0) racc[col] = acc;
    __syncthreads();
    const int idx = b * P_ + part;
    if (tid == 0) {
        float s = 0.f;
        for (int i = 0; i < 16; i++) s += red[i];
        g_att_d[idx] = s;
        g_att_m[idx] = m;
    }
    if (half == 1) g_att_acc[(size_t)idx * 256 + col] = racc[col] + acc;
}

// ---------------- attention combine ----------------
__global__ __launch_bounds__(256) void k_attn_comb(float* __restrict__ qstar)
{
    const int b = blockIdx.x, col = threadIdx.x;
    __shared__ float sc[P_];
    __shared__ float sdenom;
    if (col == 0) {
        float m = -INFINITY;
#pragma unroll
        for (int p = 0; p < P_; p++) m = fmaxf(m, g_att_m[b * P_ + p]);
        if (!isfinite(m)) m = 0.f;
        float denom = 0.f;
#pragma unroll
        for (int p = 0; p < P_; p++) {
            float e = expf(g_att_m[b * P_ + p] - m);
            sc[p] = e;
            denom += g_att_d[b * P_ + p] * e;
        }
        sdenom = denom + 1e-16f;
    }
    __syncthreads();
    float r = 0.f;
#pragma unroll
    for (int p = 0; p < P_; p++)
        r += sc[p] * g_att_acc[(size_t)(b * P_ + p) * 256 + col];
    qstar[b * 2 * H_ + 256 + col] = r / sdenom;
}

// ---------------- output projection ----------------
__global__ void k_out(const float* __restrict__ qstar, const float* __restrict__ W,
                      const float* __restrict__ bias, float* __restrict__ out)
{
    int b = blockIdx.x, e = threadIdx.x;
    __shared__ float qs[512];
    qs[e] = qstar[b * 512 + e];
    qs[e + 128] = qstar[b * 512 + e + 128];
    qs[e + 256] = qstar[b * 512 + e + 256];
    qs[e + 384] = qstar[b * 512 + e + 384];
    __syncthreads();
    float acc = bias[e];
#pragma unroll 8
    for (int k = 0; k < 512; k++) acc += qs[k] * W[k * E_ + e];
    out[b * E_ + e] = acc;
}

// ---------------- launch ----------------
extern "C" void kernel_launch(void* const* d_in, const int* in_sizes, int n_in,
                              void* d_out, int out_size)
{
    const float* x    = (const float*)d_in[0];
    const int*   bidx = (const int*)d_in[1];
    const float* W1   = (const float*)d_in[2];
    const float* b1   = (const float*)d_in[3];
    const float* W2   = (const float*)d_in[4];
    const float* b2   = (const float*)d_in[5];
    const float* Wih[3] = {(const float*)d_in[6],  (const float*)d_in[10], (const float*)d_in[14]};
    const float* Whh[3] = {(const float*)d_in[7],  (const float*)d_in[11], (const float*)d_in[15]};
    const float* bih[3] = {(const float*)d_in[8],  (const float*)d_in[12], (const float*)d_in[16]};
    const float* bhh[3] = {(const float*)d_in[9],  (const float*)d_in[13], (const float*)d_in[17]};
    const float* outW = (const float*)d_in[18];
    const float* outb = (const float*)d_in[19];
    float* out = (float*)d_out;

    const int N = in_sizes[0] / D_;

    float *hfeat_p, *gpart_p, *hbuf_p, *c_p, *qstar_p, *wt1_p, *wt2_p;
    cudaGetSymbolAddress((void**)&hfeat_p, g_hfeat);
    cudaGetSymbolAddress((void**)&gpart_p, g_gpart);
    cudaGetSymbolAddress((void**)&hbuf_p,  g_hbuf);
    cudaGetSymbolAddress((void**)&c_p,     g_c);
    cudaGetSymbolAddress((void**)&qstar_p, g_qstar);
    cudaGetSymbolAddress((void**)&wt1_p,   g_Wt1);
    cudaGetSymbolAddress((void**)&wt2_p,   g_Wt2);

    cudaFuncSetAttribute(k_fnn_fused, cudaFuncAttributeMaxDynamicSharedMemorySize, FSMEM);

    k_init<<<256, 256>>>();
    k_seg<<<1, B_ + 1>>>(bidx, N);
    dim3 tb(32, 32);
    dim3 tg(8, 8, 2);
    k_transpose<<<tg, tb>>>(W1, W2, wt1_p, wt2_p);

    k_fnn_fused<<<(N + 127) / 128, 512, FSMEM>>>(x, wt1_p, wt2_p, b1, b2, hfeat_p, N);

    for (int s = 0; s < STEPS_; s++) {
        float* hold = hbuf_p + (size_t)(s & 1) * 3 * B_ * H_;
        float* hnew = hbuf_p + (size_t)((s & 1) ^ 1) * 3 * B_ * H_;
        for (int l = 0; l < 3; l++) {
            const float* xin = (l == 0) ? (const float*)qstar_p
                                        : (const float*)(hnew + (size_t)(l - 1) * B_ * H_);
            int KW = (l == 0) ? 2 * H_ : H_;
            dim3 gg(B_ / 32, 4 * H_ / 32, 2);
            k_gates<<<gg, 256>>>(xin, KW, hold + (size_t)l * B_ * H_,
                                 Wih[l], Whh[l], gpart_p);
            k_update<<<B_, H_>>>(gpart_p, gpart_p + (size_t)B_ * 4 * H_,
                                 bih[l], bhh[l],
                                 c_p + (size_t)l * B_ * H_,
                                 hnew + (size_t)l * B_ * H_,
                                 (l == 2) ? qstar_p : nullptr);
        }
        dim3 ag(B_, P_);
        k_attn_part<<<ag, 512>>>(hfeat_p, hnew + (size_t)2 * B_ * H_);
        k_attn_comb<<<B_, 256>>>(qstar_p);
    }
    k_out<<<B_, E_>>>(qstar_p, outW, outb, out);
}